// round 1
// baseline (speedup 1.0000x reference)
#include <cuda_runtime.h>
#include <math.h>

#define B_ 8
#define N_ 2048
#define H_ 1024
#define E_ 8
#define D_ 2048
#define T_ 16384   // B_*N_

// ---------------- scratch (allocation-free: __device__ globals) ----------------
__device__ int   g_expert_idx[T_];
__device__ int   g_counts[E_];
__device__ int   g_offsets[E_ + 1];
__device__ int   g_cursor[E_];
__device__ int   g_token_list[T_];
__device__ float g_prob_sum[E_];
__device__ float g_entropy_sum;
__device__ float g_Hbuf[(size_t)T_ * D_];   // 128 MiB intermediate GELU activations

// ---------------- init ----------------
__global__ void init_kernel() {
    int i = threadIdx.x;
    if (i < E_) { g_counts[i] = 0; g_cursor[i] = 0; g_prob_sum[i] = 0.f; }
    if (i == 0) g_entropy_sum = 0.f;
}

// ---------------- router: logits -> softmax -> argmax + loss partials ----------------
__global__ void router_kernel(const float* __restrict__ x,
                              const float* __restrict__ Wr,
                              const float* __restrict__ br) {
    __shared__ float sWr[H_ * E_];   // 32 KB
    for (int i = threadIdx.x; i < H_ * E_; i += blockDim.x) sWr[i] = Wr[i];
    __syncthreads();

    int warp = threadIdx.x >> 5;
    int lane = threadIdx.x & 31;
    int t = blockIdx.x * 8 + warp;
    if (t >= T_) return;

    const float* xr = x + (size_t)t * H_;
    float acc[E_];
#pragma unroll
    for (int e = 0; e < E_; e++) acc[e] = 0.f;

    for (int h = lane; h < H_; h += 32) {
        float xv = xr[h];
        const float* w = &sWr[h * E_];
#pragma unroll
        for (int e = 0; e < E_; e++) acc[e] += xv * w[e];
    }
#pragma unroll
    for (int e = 0; e < E_; e++) {
#pragma unroll
        for (int o = 16; o > 0; o >>= 1)
            acc[e] += __shfl_xor_sync(0xffffffffu, acc[e], o);
    }

    if (lane == 0) {
        float lg[E_];
        float mx = -1e30f;
        int arg = 0;
#pragma unroll
        for (int e = 0; e < E_; e++) {
            lg[e] = acc[e] + br[e];
            if (lg[e] > mx) { mx = lg[e]; arg = e; }   // strict > : first max (jnp.argmax)
        }
        float s = 0.f;
#pragma unroll
        for (int e = 0; e < E_; e++) { lg[e] = expf(lg[e] - mx); s += lg[e]; }
        float inv = 1.f / s;
        float ent = 0.f;
#pragma unroll
        for (int e = 0; e < E_; e++) {
            float p = lg[e] * inv;
            atomicAdd(&g_prob_sum[e], p);
            ent -= p * logf(p + 1e-8f);
        }
        atomicAdd(&g_entropy_sum, ent);
        atomicAdd(&g_counts[arg], 1);
        g_expert_idx[t] = arg;
    }
}

// ---------------- tiny exclusive scan over 8 experts ----------------
__global__ void scan_kernel() {
    if (threadIdx.x == 0) {
        int o = 0;
        for (int e = 0; e < E_; e++) {
            g_offsets[e] = o;
            g_cursor[e]  = o;
            o += g_counts[e];
        }
        g_offsets[E_] = o;
    }
}

// ---------------- scatter token ids into per-expert contiguous lists ----------------
__global__ void scatter_kernel() {
    int t = blockIdx.x * blockDim.x + threadIdx.x;
    if (t < T_) {
        int e = g_expert_idx[t];
        int pos = atomicAdd(&g_cursor[e], 1);
        g_token_list[pos] = t;
    }
}

// ---------------- grouped SGEMM: 128x128x8 tile, 8x8 microtile, 256 threads ----------------
// GELU=true : C = gelu(gather(x) @ W1[e] + b1[e]) -> g_Hbuf (scattered by token id)
// GELU=false: out[t] = gather(g_Hbuf) @ W2[e] + b2[e] + x[t]
template<int KDIM, int NDIM, bool GELU>
__global__ __launch_bounds__(256) void gemm_kernel(
    const float* __restrict__ Aparam,   // x for GEMM1; ignored for GEMM2
    const float* __restrict__ Wsrc,     // W1 or W2, [E][KDIM][NDIM] row-major
    const float* __restrict__ bias,     // b1 [E][NDIM] or b2 [E][NDIM]
    const float* __restrict__ xres,     // x for residual (GEMM2)
    float* __restrict__ outp)           // d_out (GEMM2)
{
    const int e = blockIdx.z;
    const int base  = g_offsets[e];
    const int count = g_offsets[e + 1] - base;
    const int m0 = blockIdx.y * 128;
    if (m0 >= count) return;
    const int n0 = blockIdx.x * 128;

    const float* Asrc = GELU ? Aparam : g_Hbuf;

    __shared__ float As[8][132];   // +4 pad kills store bank conflicts
    __shared__ float Bs[8][128];
    __shared__ int   sTok[128];

    const int tid = threadIdx.x;
    if (tid < 128) {
        int i = m0 + tid;
        sTok[tid] = (i < count) ? g_token_list[base + i] : -1;
    }
    __syncthreads();

    const float* Wp = Wsrc + (size_t)e * KDIM * NDIM + n0;

    const int ar = tid >> 1;            // A row 0..127
    const int ak = (tid & 1) * 4;       // A k-offset 0/4
    const int atok = sTok[ar];
    const float* Arow = (atok >= 0) ? (Asrc + (size_t)atok * KDIM) : nullptr;
    const int brow = tid >> 5;          // B row 0..7
    const int bcol = (tid & 31) * 4;    // B col 0..124

    const int tr = tid >> 4;            // 0..15
    const int tc = tid & 15;            // 0..15

    float acc[8][8];
#pragma unroll
    for (int i = 0; i < 8; i++)
#pragma unroll
        for (int j = 0; j < 8; j++) acc[i][j] = 0.f;

    for (int kt = 0; kt < KDIM; kt += 8) {
        float4 av = make_float4(0.f, 0.f, 0.f, 0.f);
        if (Arow) av = *reinterpret_cast<const float4*>(Arow + kt + ak);
        float4 bv = *reinterpret_cast<const float4*>(Wp + (size_t)(kt + brow) * NDIM + bcol);

        __syncthreads();   // previous tile's compute done
        As[ak + 0][ar] = av.x;
        As[ak + 1][ar] = av.y;
        As[ak + 2][ar] = av.z;
        As[ak + 3][ar] = av.w;
        *reinterpret_cast<float4*>(&Bs[brow][bcol]) = bv;
        __syncthreads();

#pragma unroll
        for (int kk = 0; kk < 8; kk++) {
            float a[8], b[8];
#pragma unroll
            for (int i = 0; i < 8; i++) a[i] = As[kk][tr * 8 + i];
            float4 b0 = *reinterpret_cast<const float4*>(&Bs[kk][tc * 8]);
            float4 b1v = *reinterpret_cast<const float4*>(&Bs[kk][tc * 8 + 4]);
            b[0] = b0.x;  b[1] = b0.y;  b[2] = b0.z;  b[3] = b0.w;
            b[4] = b1v.x; b[5] = b1v.y; b[6] = b1v.z; b[7] = b1v.w;
#pragma unroll
            for (int i = 0; i < 8; i++)
#pragma unroll
                for (int j = 0; j < 8; j++) acc[i][j] += a[i] * b[j];
        }
    }

    // epilogue
#pragma unroll
    for (int i = 0; i < 8; i++) {
        int ml = tr * 8 + i;
        int tok = sTok[ml];
        if (tok < 0) continue;
#pragma unroll
        for (int j = 0; j < 8; j++) {
            int n = n0 + tc * 8 + j;
            float v = acc[i][j] + bias[(size_t)e * NDIM + n];
            if (GELU) {
                v = 0.5f * v * (1.0f + erff(v * 0.7071067811865476f));
                g_Hbuf[(size_t)tok * NDIM + n] = v;
            } else {
                outp[(size_t)tok * NDIM + n] = v + xres[(size_t)tok * NDIM + n];
            }
        }
    }
}

// ---------------- losses + counts ----------------
__global__ void finalize_kernel(float* __restrict__ out, int out_size) {
    if (threadIdx.x == 0) {
        long long base = (long long)T_ * H_;
        if ((long long)out_size >= base + 2) {
            float s = 0.f;
            for (int e = 0; e < E_; e++) {
                float p = g_prob_sum[e] / (float)T_;
                s += p * p;
            }
            out[base]     = (float)E_ * s;            // balance_loss
            out[base + 1] = g_entropy_sum / (float)T_; // entropy_loss
        }
        if ((long long)out_size >= base + 2 + E_) {
            for (int e = 0; e < E_; e++)
                out[base + 2 + e] = (float)g_counts[e]; // tokens_per_expert
        }
    }
}

// ---------------- launch ----------------
extern "C" void kernel_launch(void* const* d_in, const int* in_sizes, int n_in,
                              void* d_out, int out_size) {
    const float* x  = (const float*)d_in[0];
    const float* Wr = (const float*)d_in[1];
    const float* br = (const float*)d_in[2];
    const float* W1 = (const float*)d_in[3];
    const float* b1 = (const float*)d_in[4];
    const float* W2 = (const float*)d_in[5];
    const float* b2 = (const float*)d_in[6];
    float* out = (float*)d_out;

    init_kernel<<<1, 32>>>();
    router_kernel<<<T_ / 8, 256>>>(x, Wr, br);
    scan_kernel<<<1, 32>>>();
    scatter_kernel<<<T_ / 256, 256>>>();
    gemm_kernel<H_, D_, true ><<<dim3(D_ / 128, T_ / 128, E_), 256>>>(x, W1, b1, x, out);
    gemm_kernel<D_, H_, false><<<dim3(H_ / 128, T_ / 128, E_), 256>>>(x, W2, b2, x, out);
    finalize_kernel<<<1, 32>>>(out, out_size);
}

// round 4
// speedup vs baseline: 2.9369x; 2.9369x over previous
#include <cuda_runtime.h>
#include <math.h>
#include <stdint.h>

#define B_ 8
#define N_ 2048
#define H_ 1024
#define E_ 8
#define D_ 2048
#define T_ 16384   // B_*N_
#define TPAD_ (T_ + 1024)

// ---------------- scratch (allocation-free: __device__ globals) ----------------
// NOTE: these are referenced ONLY from device code (host-passing a __device__
// symbol passes the host shadow address — on GB300 ATS that silently reads
// host BSS instead of faulting; that was the R3 bug).
__device__ int   g_expert_idx[T_];
__device__ int   g_counts[E_];
__device__ int   g_offsets[E_ + 1];
__device__ int   g_poffsets[E_ + 1];
__device__ int   g_cursor[E_];
__device__ int   g_token_list[T_];
__device__ int   g_ptok[TPAD_];
__device__ float g_prob_sum[E_];
__device__ float g_entropy_sum;
__device__ float g_Xperm[(size_t)TPAD_ * H_];   // gathered tf32 tokens (padded per expert)
__device__ float g_Hbuf[(size_t)TPAD_ * D_];    // GELU activations (tf32), padded row order
__device__ float g_W1t[(size_t)E_ * H_ * D_];   // W1 transposed to [E][D][H] tf32
__device__ float g_W2t[(size_t)E_ * D_ * H_];   // W2 transposed to [E][H][D] tf32

// ---------------- helpers ----------------
__device__ __forceinline__ uint32_t smem_u32(const void* p) {
    uint32_t a;
    asm("{ .reg .u64 t; cvta.to.shared.u64 t, %1; cvt.u32.u64 %0, t; }" : "=r"(a) : "l"(p));
    return a;
}
__device__ __forceinline__ float to_tf32(float x) {
    uint32_t u;
    asm("cvt.rna.tf32.f32 %0, %1;" : "=r"(u) : "f"(x));
    return __uint_as_float(u);
}
__device__ __forceinline__ void cp_async16(uint32_t dst, const void* src) {
    asm volatile("cp.async.cg.shared.global [%0], [%1], 16;" :: "r"(dst), "l"(src));
}
#define CP_COMMIT() asm volatile("cp.async.commit_group;" ::: "memory")
#define CP_WAIT1()  asm volatile("cp.async.wait_group 1;" ::: "memory")
#define CP_WAIT0()  asm volatile("cp.async.wait_group 0;" ::: "memory")

__device__ __forceinline__ void mma_tf32_16x8x8(float& d0, float& d1, float& d2, float& d3,
                                                uint32_t a0, uint32_t a1, uint32_t a2, uint32_t a3,
                                                uint32_t b0, uint32_t b1) {
    asm volatile(
        "mma.sync.aligned.m16n8k8.row.col.f32.tf32.tf32.f32 "
        "{%0,%1,%2,%3}, {%4,%5,%6,%7}, {%8,%9}, {%0,%1,%2,%3};"
        : "+f"(d0), "+f"(d1), "+f"(d2), "+f"(d3)
        : "r"(a0), "r"(a1), "r"(a2), "r"(a3), "r"(b0), "r"(b1));
}

// ---------------- init ----------------
__global__ void init_kernel() {
    int i = threadIdx.x;
    if (i < E_) { g_counts[i] = 0; g_cursor[i] = 0; g_prob_sum[i] = 0.f; }
    if (i == 0) g_entropy_sum = 0.f;
}

// ---------------- router ----------------
__global__ void router_kernel(const float* __restrict__ x,
                              const float* __restrict__ Wr,
                              const float* __restrict__ br) {
    __shared__ float sWr[H_ * E_];
    for (int i = threadIdx.x; i < H_ * E_; i += blockDim.x) sWr[i] = Wr[i];
    __syncthreads();

    int warp = threadIdx.x >> 5;
    int lane = threadIdx.x & 31;
    int t = blockIdx.x * 8 + warp;
    if (t >= T_) return;

    const float* xr = x + (size_t)t * H_;
    float acc[E_];
#pragma unroll
    for (int e = 0; e < E_; e++) acc[e] = 0.f;
    for (int h = lane; h < H_; h += 32) {
        float xv = xr[h];
        const float* w = &sWr[h * E_];
#pragma unroll
        for (int e = 0; e < E_; e++) acc[e] += xv * w[e];
    }
#pragma unroll
    for (int e = 0; e < E_; e++) {
#pragma unroll
        for (int o = 16; o > 0; o >>= 1)
            acc[e] += __shfl_xor_sync(0xffffffffu, acc[e], o);
    }
    if (lane == 0) {
        float lg[E_];
        float mx = -1e30f;
        int arg = 0;
#pragma unroll
        for (int e = 0; e < E_; e++) {
            lg[e] = acc[e] + br[e];
            if (lg[e] > mx) { mx = lg[e]; arg = e; }
        }
        float s = 0.f;
#pragma unroll
        for (int e = 0; e < E_; e++) { lg[e] = expf(lg[e] - mx); s += lg[e]; }
        float inv = 1.f / s;
        float ent = 0.f;
#pragma unroll
        for (int e = 0; e < E_; e++) {
            float p = lg[e] * inv;
            atomicAdd(&g_prob_sum[e], p);
            ent -= p * logf(p + 1e-8f);
        }
        atomicAdd(&g_entropy_sum, ent);
        atomicAdd(&g_counts[arg], 1);
        g_expert_idx[t] = arg;
    }
}

// ---------------- scan ----------------
__global__ void scan_kernel() {
    if (threadIdx.x == 0) {
        int o = 0, po = 0;
        for (int e = 0; e < E_; e++) {
            g_offsets[e] = o;
            g_cursor[e] = o;
            g_poffsets[e] = po;
            o += g_counts[e];
            po += (g_counts[e] + 127) & ~127;
        }
        g_offsets[E_] = o;
        g_poffsets[E_] = po;
    }
}

// ---------------- scatter ----------------
__global__ void scatter_kernel() {
    int t = blockIdx.x * blockDim.x + threadIdx.x;
    if (t < T_) {
        int e = g_expert_idx[t];
        int pos = atomicAdd(&g_cursor[e], 1);
        g_token_list[pos] = t;
    }
}

// ---------------- W transpose + tf32 round: W[e][k][n] -> Wt[e][n][k] ----------------
// WHICH=0: W1 [E][H][D] -> g_W1t [E][D][H];  WHICH=1: W2 [E][D][H] -> g_W2t [E][H][D]
template<int WHICH>
__global__ void wconv_kernel(const float* __restrict__ W, int K, int Ncols) {
    float* Wt = WHICH ? g_W2t : g_W1t;   // device-side symbol -> real device address
    __shared__ float t[32][33];
    int e = blockIdx.z;
    int nb = blockIdx.x * 32;
    int kb = blockIdx.y * 32;
    int tx = threadIdx.x & 31;
    int ty = threadIdx.x >> 5;   // 0..7
    const float* Wp = W + (size_t)e * K * Ncols;
    float* Wtp = Wt + (size_t)e * K * Ncols;
#pragma unroll
    for (int i = 0; i < 32; i += 8)
        t[ty + i][tx] = Wp[(size_t)(kb + ty + i) * Ncols + nb + tx];
    __syncthreads();
#pragma unroll
    for (int i = 0; i < 32; i += 8)
        Wtp[(size_t)(nb + ty + i) * K + kb + tx] = to_tf32(t[tx][ty + i]);
}

// ---------------- gather x -> Xperm (tf32), build ptok, zero pad rows ----------------
__global__ void gatherx_kernel(const float* __restrict__ x) {
    int p = blockIdx.x;
    if (p >= g_poffsets[E_]) return;
    int e = 0;
#pragma unroll
    for (int i = 1; i < E_; i++)
        if (p >= g_poffsets[i]) e = i;
    int local = p - g_poffsets[e];
    int cnt = g_counts[e];
    int tok = (local < cnt) ? g_token_list[g_offsets[e] + local] : -1;
    if (threadIdx.x == 0) g_ptok[p] = tok;
    float4* dst = reinterpret_cast<float4*>(g_Xperm + (size_t)p * H_);
    if (tok >= 0) {
        const float4* src = reinterpret_cast<const float4*>(x + (size_t)tok * H_);
        for (int i = threadIdx.x; i < H_ / 4; i += blockDim.x) {
            float4 v = src[i];
            v.x = to_tf32(v.x); v.y = to_tf32(v.y);
            v.z = to_tf32(v.z); v.w = to_tf32(v.w);
            dst[i] = v;
        }
    } else {
        float4 z = make_float4(0.f, 0.f, 0.f, 0.f);
        for (int i = threadIdx.x; i < H_ / 4; i += blockDim.x) dst[i] = z;
    }
}

// ---------------- mma.sync tf32 grouped GEMM ----------------
// Block tile 128(M) x 256(N), K_CHUNK=32, 3-stage cp.async pipeline.
// 8 warps in 2(M) x 4(N); warp tile 64x64 = 4 m-frags x 8 n-frags of m16n8k8.
// GELU=true : A=g_Xperm, Wt=g_W1t; Hbuf[p][n] = tf32(gelu(A@Wt^T + b))
// GELU=false: A=g_Hbuf,  Wt=g_W2t; out[tok][n] = A@Wt^T + b + x[tok][n]
#define STAGES   3
#define A_ROWS   128
#define B_ROWS   256
#define KC       32
#define PADK     36                       // floats per SMEM row (bank-conflict-free)
#define A_F      (A_ROWS * PADK)          // 4608 floats
#define B_F      (B_ROWS * PADK)          // 9216 floats
#define STAGE_F  (A_F + B_F)              // 13824 floats
#define GEMM_SMEM (STAGES * STAGE_F * 4)  // 165888 bytes

template<int KTOT, int NTOT, bool GELU>
__global__ void __launch_bounds__(256, 1)
moe_gemm(const float* __restrict__ bias,
         const float* __restrict__ xres,
         float* __restrict__ outp)
{
    constexpr int CCH = KTOT / KC;
    const float* A  = GELU ? g_Xperm : g_Hbuf;   // device-side symbols
    const float* Wt = GELU ? g_W1t   : g_W2t;

    const int e = blockIdx.z;
    const int pbase = g_poffsets[e];
    const int pcount = g_poffsets[e + 1] - pbase;
    const int m0 = blockIdx.y * 128;
    if (m0 >= pcount) return;
    const int n0 = blockIdx.x * 256;

    extern __shared__ float sm[];
    const uint32_t smbase = smem_u32(sm);

    const int tid = threadIdx.x;
    const int wid = tid >> 5;
    const int lane = tid & 31;
    const int grp = lane >> 2;     // 0..7
    const int qid = lane & 3;      // 0..3
    const int mrow = (wid & 1) * 64;
    const int nrow = (wid >> 1) * 64;

    // per-thread cp.async source pointers + SMEM byte offsets
    const char* aptr[4];
    uint32_t aoff[4];
    {
        const float* Ab = A + (size_t)(pbase + m0) * KTOT;
#pragma unroll
        for (int i = 0; i < 4; i++) {
            int idx = tid + i * 256;          // 0..1023
            int row = idx >> 3, c = idx & 7;  // row 0..127, 16B chunk 0..7
            aptr[i] = reinterpret_cast<const char*>(Ab + (size_t)row * KTOT) + c * 16;
            aoff[i] = (uint32_t)(row * PADK + c * 4) * 4;
        }
    }
    const char* bptr[8];
    uint32_t boff[8];
    {
        const float* Bb = Wt + ((size_t)e * NTOT + n0) * KTOT;
#pragma unroll
        for (int i = 0; i < 8; i++) {
            int idx = tid + i * 256;          // 0..2047
            int row = idx >> 3, c = idx & 7;  // row 0..255
            bptr[i] = reinterpret_cast<const char*>(Bb + (size_t)row * KTOT) + c * 16;
            boff[i] = (uint32_t)(A_F + row * PADK + c * 4) * 4;
        }
    }

#define LOAD_STAGE(st, ch) do {                                                     \
        uint32_t _sb = smbase + (uint32_t)(st) * (STAGE_F * 4);                     \
        size_t _go = (size_t)(ch) * (KC * 4);                                       \
        _Pragma("unroll")                                                           \
        for (int _i = 0; _i < 4; _i++) cp_async16(_sb + aoff[_i], aptr[_i] + _go);  \
        _Pragma("unroll")                                                           \
        for (int _i = 0; _i < 8; _i++) cp_async16(_sb + boff[_i], bptr[_i] + _go);  \
    } while (0)

    float acc[4][8][4];
#pragma unroll
    for (int i = 0; i < 4; i++)
#pragma unroll
        for (int j = 0; j < 8; j++)
#pragma unroll
            for (int q = 0; q < 4; q++) acc[i][j][q] = 0.f;

    // preload stages 0,1
    LOAD_STAGE(0, 0); CP_COMMIT();
    LOAD_STAGE(1, 1); CP_COMMIT();

    for (int c = 0; c < CCH; c++) {
        CP_WAIT1();            // chunk c resident
        __syncthreads();       // all warps done with stage being overwritten next
        if (c + 2 < CCH) LOAD_STAGE((c + 2) % STAGES, c + 2);
        CP_COMMIT();           // real or empty group (keeps wait accounting uniform)

        const float* As = sm + (c % STAGES) * STAGE_F;
        const float* Bs = As + A_F;

#pragma unroll
        for (int ks = 0; ks < 4; ks++) {
            const int k0 = ks * 8;
            uint32_t a[4][4], b[8][2];
#pragma unroll
            for (int fm = 0; fm < 4; fm++) {
                const int r = mrow + fm * 16 + grp;
                a[fm][0] = __float_as_uint(As[r * PADK + k0 + qid]);
                a[fm][1] = __float_as_uint(As[(r + 8) * PADK + k0 + qid]);
                a[fm][2] = __float_as_uint(As[r * PADK + k0 + qid + 4]);
                a[fm][3] = __float_as_uint(As[(r + 8) * PADK + k0 + qid + 4]);
            }
#pragma unroll
            for (int fn = 0; fn < 8; fn++) {
                const int r = nrow + fn * 8 + grp;
                b[fn][0] = __float_as_uint(Bs[r * PADK + k0 + qid]);
                b[fn][1] = __float_as_uint(Bs[r * PADK + k0 + qid + 4]);
            }
#pragma unroll
            for (int fm = 0; fm < 4; fm++)
#pragma unroll
                for (int fn = 0; fn < 8; fn++)
                    mma_tf32_16x8x8(acc[fm][fn][0], acc[fm][fn][1],
                                    acc[fm][fn][2], acc[fm][fn][3],
                                    a[fm][0], a[fm][1], a[fm][2], a[fm][3],
                                    b[fn][0], b[fn][1]);
        }
    }
    CP_WAIT0();

    // ---- epilogue: registers -> global, fused bias (+gelu | +residual) ----
    // c0,c1 at (row=grp, col=2*qid, 2*qid+1); c2,c3 at row=grp+8.
    int toks[4][2];
    if (!GELU) {
#pragma unroll
        for (int fm = 0; fm < 4; fm++) {
            toks[fm][0] = g_ptok[pbase + m0 + mrow + fm * 16 + grp];
            toks[fm][1] = g_ptok[pbase + m0 + mrow + fm * 16 + grp + 8];
        }
    }

#pragma unroll
    for (int fn = 0; fn < 8; fn++) {
        const int col = n0 + nrow + fn * 8 + qid * 2;
        const float2 bv = *reinterpret_cast<const float2*>(bias + (size_t)e * NTOT + col);
#pragma unroll
        for (int fm = 0; fm < 4; fm++) {
#pragma unroll
            for (int h = 0; h < 2; h++) {
                float v0 = acc[fm][fn][h * 2 + 0] + bv.x;
                float v1 = acc[fm][fn][h * 2 + 1] + bv.y;
                if (GELU) {
                    const int prow = pbase + m0 + mrow + fm * 16 + grp + h * 8;
                    v0 = 0.5f * v0 * (1.0f + erff(v0 * 0.7071067811865476f));
                    v1 = 0.5f * v1 * (1.0f + erff(v1 * 0.7071067811865476f));
                    float2 o = make_float2(to_tf32(v0), to_tf32(v1));
                    *reinterpret_cast<float2*>(g_Hbuf + (size_t)prow * NTOT + col) = o;
                } else {
                    const int tok = toks[fm][h];
                    if (tok >= 0) {
                        const float2 xr = *reinterpret_cast<const float2*>(
                            xres + (size_t)tok * NTOT + col);
                        float2 o = make_float2(v0 + xr.x, v1 + xr.y);
                        *reinterpret_cast<float2*>(outp + (size_t)tok * NTOT + col) = o;
                    }
                }
            }
        }
    }
#undef LOAD_STAGE
}

// ---------------- losses ----------------
__global__ void finalize_kernel(float* __restrict__ out, int out_size) {
    if (threadIdx.x == 0) {
        long long base = (long long)T_ * H_;
        if ((long long)out_size >= base + 2) {
            float s = 0.f;
            for (int e = 0; e < E_; e++) {
                float p = g_prob_sum[e] / (float)T_;
                s += p * p;
            }
            out[base] = (float)E_ * s;
            out[base + 1] = g_entropy_sum / (float)T_;
        }
        if ((long long)out_size >= base + 2 + E_) {
            for (int e = 0; e < E_; e++)
                out[base + 2 + e] = (float)g_counts[e];
        }
    }
}

// ---------------- launch ----------------
extern "C" void kernel_launch(void* const* d_in, const int* in_sizes, int n_in,
                              void* d_out, int out_size) {
    const float* x  = (const float*)d_in[0];
    const float* Wr = (const float*)d_in[1];
    const float* br = (const float*)d_in[2];
    const float* W1 = (const float*)d_in[3];
    const float* b1 = (const float*)d_in[4];
    const float* W2 = (const float*)d_in[5];
    const float* b2 = (const float*)d_in[6];
    float* out = (float*)d_out;

    cudaFuncSetAttribute(moe_gemm<H_, D_, true>,
                         cudaFuncAttributeMaxDynamicSharedMemorySize, GEMM_SMEM);
    cudaFuncSetAttribute(moe_gemm<D_, H_, false>,
                         cudaFuncAttributeMaxDynamicSharedMemorySize, GEMM_SMEM);

    init_kernel<<<1, 32>>>();
    router_kernel<<<T_ / 8, 256>>>(x, Wr, br);
    scan_kernel<<<1, 1>>>();
    scatter_kernel<<<T_ / 256, 256>>>();
    wconv_kernel<0><<<dim3(D_ / 32, H_ / 32, E_), 256>>>(W1, H_, D_);
    wconv_kernel<1><<<dim3(H_ / 32, D_ / 32, E_), 256>>>(W2, D_, H_);
    gatherx_kernel<<<TPAD_, 128>>>(x);
    moe_gemm<H_, D_, true ><<<dim3(D_ / 256, T_ / 128, E_), 256, GEMM_SMEM>>>(b1, x, out);
    moe_gemm<D_, H_, false><<<dim3(H_ / 256, T_ / 128, E_), 256, GEMM_SMEM>>>(b2, x, out);
    finalize_kernel<<<1, 32>>>(out, out_size);
}

// round 5
// speedup vs baseline: 3.0069x; 1.0238x over previous
#include <cuda_runtime.h>
#include <math.h>
#include <stdint.h>

#define B_ 8
#define N_ 2048
#define H_ 1024
#define E_ 8
#define D_ 2048
#define T_ 16384   // B_*N_
#define TPAD_ (T_ + 1024)

// ---------------- scratch (device-side referenced ONLY from device code) ----------------
__device__ int   g_expert_idx[T_];
__device__ int   g_counts[E_];
__device__ int   g_offsets[E_ + 1];
__device__ int   g_poffsets[E_ + 1];
__device__ int   g_cursor[E_];
__device__ int   g_ptok[TPAD_];
__device__ float g_prob_sum[E_];
__device__ float g_entropy_sum;
__device__ volatile int g_flag;
__device__ float g_Hbuf[(size_t)TPAD_ * D_];    // GELU activations (fp32), padded row order

// ---------------- helpers ----------------
__device__ __forceinline__ uint32_t smem_u32(const void* p) {
    uint32_t a;
    asm("{ .reg .u64 t; cvta.to.shared.u64 t, %1; cvt.u32.u64 %0, t; }" : "=r"(a) : "l"(p));
    return a;
}
__device__ __forceinline__ uint32_t tf32_bits(float x) {   // RNA round to tf32
    uint32_t u;
    asm("cvt.rna.tf32.f32 %0, %1;" : "=r"(u) : "f"(x));
    return u;
}
__device__ __forceinline__ void cp_async16(uint32_t dst, const void* src) {
    asm volatile("cp.async.cg.shared.global [%0], [%1], 16;" :: "r"(dst), "l"(src));
}
__device__ __forceinline__ void cp_async16z(uint32_t dst, const void* src, uint32_t sz) {
    asm volatile("cp.async.cg.shared.global [%0], [%1], 16, %2;" :: "r"(dst), "l"(src), "r"(sz));
}
#define CP_COMMIT() asm volatile("cp.async.commit_group;" ::: "memory")
#define CP_WAIT1()  asm volatile("cp.async.wait_group 1;" ::: "memory")
#define CP_WAIT0()  asm volatile("cp.async.wait_group 0;" ::: "memory")

__device__ __forceinline__ void mma_tf32_16x8x8(float& d0, float& d1, float& d2, float& d3,
                                                uint32_t a0, uint32_t a1, uint32_t a2, uint32_t a3,
                                                uint32_t b0, uint32_t b1) {
    asm volatile(
        "mma.sync.aligned.m16n8k8.row.col.f32.tf32.tf32.f32 "
        "{%0,%1,%2,%3}, {%4,%5,%6,%7}, {%8,%9}, {%0,%1,%2,%3};"
        : "+f"(d0), "+f"(d1), "+f"(d2), "+f"(d3)
        : "r"(a0), "r"(a1), "r"(a2), "r"(a3), "r"(b0), "r"(b1));
}

// ---------------- init ----------------
__global__ void init_kernel() {
    int i = blockIdx.x * blockDim.x + threadIdx.x;
    if (i < E_) { g_counts[i] = 0; g_prob_sum[i] = 0.f; }
    if (i == 0) { g_entropy_sum = 0.f; g_flag = 0; }
    for (int p = i; p < TPAD_; p += gridDim.x * blockDim.x) g_ptok[p] = -1;
}

// ---------------- router ----------------
__global__ void router_kernel(const float* __restrict__ x,
                              const float* __restrict__ Wr,
                              const float* __restrict__ br) {
    __shared__ float sWr[H_ * E_];
    for (int i = threadIdx.x; i < H_ * E_; i += blockDim.x) sWr[i] = Wr[i];
    __syncthreads();

    int warp = threadIdx.x >> 5;
    int lane = threadIdx.x & 31;
    int t = blockIdx.x * 8 + warp;
    if (t >= T_) return;

    const float* xr = x + (size_t)t * H_;
    float acc[E_];
#pragma unroll
    for (int e = 0; e < E_; e++) acc[e] = 0.f;
    for (int h = lane; h < H_; h += 32) {
        float xv = xr[h];
        const float* w = &sWr[h * E_];
#pragma unroll
        for (int e = 0; e < E_; e++) acc[e] += xv * w[e];
    }
#pragma unroll
    for (int e = 0; e < E_; e++) {
#pragma unroll
        for (int o = 16; o > 0; o >>= 1)
            acc[e] += __shfl_xor_sync(0xffffffffu, acc[e], o);
    }
    if (lane == 0) {
        float lg[E_];
        float mx = -1e30f;
        int arg = 0;
#pragma unroll
        for (int e = 0; e < E_; e++) {
            lg[e] = acc[e] + br[e];
            if (lg[e] > mx) { mx = lg[e]; arg = e; }
        }
        float s = 0.f;
#pragma unroll
        for (int e = 0; e < E_; e++) { lg[e] = expf(lg[e] - mx); s += lg[e]; }
        float inv = 1.f / s;
        float ent = 0.f;
#pragma unroll
        for (int e = 0; e < E_; e++) {
            float p = lg[e] * inv;
            atomicAdd(&g_prob_sum[e], p);
            ent -= p * logf(p + 1e-8f);
        }
        atomicAdd(&g_entropy_sum, ent);
        atomicAdd(&g_counts[arg], 1);
        g_expert_idx[t] = arg;
    }
}

// ---------------- scan + scatter (one kernel; block0/thread0 scans, rest spin) ----------------
__global__ void scanscatter_kernel() {
    const int t = blockIdx.x * blockDim.x + threadIdx.x;
    if (t == 0) {
        int o = 0, po = 0;
        for (int e = 0; e < E_; e++) {
            g_offsets[e] = o;
            g_cursor[e] = o;
            g_poffsets[e] = po;
            o += g_counts[e];
            po += (g_counts[e] + 127) & ~127;
        }
        g_offsets[E_] = o;
        g_poffsets[E_] = po;
        __threadfence();
        g_flag = 1;
    } else {
        while (g_flag == 0) __nanosleep(64);
    }
    __threadfence();
    if (t < T_) {
        int e = g_expert_idx[t];
        int pos = atomicAdd(&g_cursor[e], 1);
        int p = g_poffsets[e] + (pos - g_offsets[e]);
        g_ptok[p] = t;
    }
}

// ---------------- mma.sync tf32 grouped GEMM, direct-from-W B tiles ----------------
// Block tile 128(M) x 256(N), K_CHUNK=32, 3-stage cp.async pipeline.
// 8 warps 2(M) x 4(N); warp tile 64x64 = 4 m-frags x 8 n-frags of m16n8k8.
// A SMEM: [128][36] k-contiguous. B SMEM: [32][264] n-contiguous (8*qid+grp banks).
// Fragments rounded to tf32 (RNA) after LDS -> unbiased, no pre-pass needed.
// GELU=true : A = gather(x) via g_ptok;   Hbuf[p][n] = gelu(A@W1 + b1)
// GELU=false: A = Hbuf (padded rows);     out[tok][n] = A@W2 + b2 + x[tok][n]
#define STAGES   3
#define KC       32
#define PADK     36
#define PADN     264
#define A_F      (128 * PADK)             // 4608 floats
#define B_F      (KC * PADN)              // 8448 floats
#define STAGE_F  (A_F + B_F)              // 13056 floats
#define GEMM_SMEM (STAGES * STAGE_F * 4)  // 156672 bytes

template<int KTOT, int NTOT, bool GELU>
__global__ void __launch_bounds__(256, 1)
moe_gemm(const float* __restrict__ xin,    // x (token source for GELU; residual always)
         const float* __restrict__ W,      // W1 or W2: [E][KTOT][NTOT], N contiguous
         const float* __restrict__ bias,
         float* __restrict__ outp)
{
    constexpr int CCH = KTOT / KC;
    const int e = blockIdx.z;
    const int pbase = g_poffsets[e];
    const int pcount = g_poffsets[e + 1] - pbase;
    const int m0 = blockIdx.y * 128;
    if (m0 >= pcount) return;
    const int n0 = blockIdx.x * 256;

    extern __shared__ float sm[];
    const uint32_t smbase = smem_u32(sm);

    const int tid = threadIdx.x;
    const int wid = tid >> 5;
    const int lane = tid & 31;
    const int grp = lane >> 2;     // 0..7
    const int qid = lane & 3;      // 0..3
    const int mrow = (wid & 1) * 64;
    const int nrow = (wid >> 1) * 64;

    // A: 4 slots x 16B per thread; row = idx>>3 (0..127), chunk col = idx&7
    const char* aptr[4];
    uint32_t aoff[4], asz[4];
#pragma unroll
    for (int i = 0; i < 4; i++) {
        int idx = tid + i * 256;
        int row = idx >> 3, c = idx & 7;
        if (GELU) {
            int tok = g_ptok[pbase + m0 + row];
            aptr[i] = reinterpret_cast<const char*>(
                          xin + (size_t)(tok < 0 ? 0 : tok) * KTOT) + c * 16;
            asz[i] = (tok < 0) ? 0u : 16u;
        } else {
            aptr[i] = reinterpret_cast<const char*>(
                          g_Hbuf + (size_t)(pbase + m0 + row) * KTOT) + c * 16;
            asz[i] = 16u;
        }
        aoff[i] = (uint32_t)(row * PADK + c * 4) * 4;
    }
    // B: 8 slots x 16B; k-row = idx>>6 (0..31), col chunk = idx&63
    const char* bptr[8];
    uint32_t boff[8];
#pragma unroll
    for (int i = 0; i < 8; i++) {
        int idx = tid + i * 256;
        int kr = idx >> 6, c = idx & 63;
        bptr[i] = reinterpret_cast<const char*>(
                      W + (size_t)e * KTOT * NTOT + (size_t)kr * NTOT + n0) + c * 16;
        boff[i] = (uint32_t)(A_F + kr * PADN + c * 4) * 4;
    }

#define LOAD_STAGE(st, ch) do {                                                          \
        uint32_t _sb = smbase + (uint32_t)(st) * (STAGE_F * 4);                          \
        size_t _ga = (size_t)(ch) * (KC * 4);                                            \
        size_t _gb = (size_t)(ch) * ((size_t)KC * NTOT * 4);                             \
        _Pragma("unroll")                                                                \
        for (int _i = 0; _i < 4; _i++) cp_async16z(_sb + aoff[_i], aptr[_i] + _ga, asz[_i]); \
        _Pragma("unroll")                                                                \
        for (int _i = 0; _i < 8; _i++) cp_async16(_sb + boff[_i], bptr[_i] + _gb);       \
    } while (0)

    float acc[4][8][4];
#pragma unroll
    for (int i = 0; i < 4; i++)
#pragma unroll
        for (int j = 0; j < 8; j++)
#pragma unroll
            for (int q = 0; q < 4; q++) acc[i][j][q] = 0.f;

    LOAD_STAGE(0, 0); CP_COMMIT();
    LOAD_STAGE(1, 1); CP_COMMIT();

    for (int c = 0; c < CCH; c++) {
        CP_WAIT1();
        __syncthreads();
        if (c + 2 < CCH) LOAD_STAGE((c + 2) % STAGES, c + 2);
        CP_COMMIT();

        const float* As = sm + (c % STAGES) * STAGE_F;
        const float* Bs = As + A_F;

#pragma unroll
        for (int ks = 0; ks < 4; ks++) {
            const int k0 = ks * 8;
            uint32_t a[4][4], b[8][2];
#pragma unroll
            for (int fm = 0; fm < 4; fm++) {
                const int r = mrow + fm * 16 + grp;
                a[fm][0] = tf32_bits(As[r * PADK + k0 + qid]);
                a[fm][1] = tf32_bits(As[(r + 8) * PADK + k0 + qid]);
                a[fm][2] = tf32_bits(As[r * PADK + k0 + qid + 4]);
                a[fm][3] = tf32_bits(As[(r + 8) * PADK + k0 + qid + 4]);
            }
#pragma unroll
            for (int fn = 0; fn < 8; fn++) {
                const int n = nrow + fn * 8 + grp;
                b[fn][0] = tf32_bits(Bs[(k0 + qid) * PADN + n]);
                b[fn][1] = tf32_bits(Bs[(k0 + qid + 4) * PADN + n]);
            }
#pragma unroll
            for (int fm = 0; fm < 4; fm++)
#pragma unroll
                for (int fn = 0; fn < 8; fn++)
                    mma_tf32_16x8x8(acc[fm][fn][0], acc[fm][fn][1],
                                    acc[fm][fn][2], acc[fm][fn][3],
                                    a[fm][0], a[fm][1], a[fm][2], a[fm][3],
                                    b[fn][0], b[fn][1]);
        }
    }
    CP_WAIT0();

    // ---- epilogue ----
    int toks[4][2];
    if (!GELU) {
#pragma unroll
        for (int fm = 0; fm < 4; fm++) {
            toks[fm][0] = g_ptok[pbase + m0 + mrow + fm * 16 + grp];
            toks[fm][1] = g_ptok[pbase + m0 + mrow + fm * 16 + grp + 8];
        }
    }

#pragma unroll
    for (int fn = 0; fn < 8; fn++) {
        const int col = n0 + nrow + fn * 8 + qid * 2;
        const float2 bv = *reinterpret_cast<const float2*>(bias + (size_t)e * NTOT + col);
#pragma unroll
        for (int fm = 0; fm < 4; fm++) {
#pragma unroll
            for (int h = 0; h < 2; h++) {
                float v0 = acc[fm][fn][h * 2 + 0] + bv.x;
                float v1 = acc[fm][fn][h * 2 + 1] + bv.y;
                if (GELU) {
                    const int prow = pbase + m0 + mrow + fm * 16 + grp + h * 8;
                    v0 = 0.5f * v0 * (1.0f + erff(v0 * 0.7071067811865476f));
                    v1 = 0.5f * v1 * (1.0f + erff(v1 * 0.7071067811865476f));
                    *reinterpret_cast<float2*>(g_Hbuf + (size_t)prow * NTOT + col) =
                        make_float2(v0, v1);
                } else {
                    const int tok = toks[fm][h];
                    if (tok >= 0) {
                        const float2 xr = *reinterpret_cast<const float2*>(
                            xin + (size_t)tok * NTOT + col);
                        *reinterpret_cast<float2*>(outp + (size_t)tok * NTOT + col) =
                            make_float2(v0 + xr.x, v1 + xr.y);
                    }
                }
            }
        }
    }
#undef LOAD_STAGE
}

// ---------------- losses ----------------
__global__ void finalize_kernel(float* __restrict__ out, int out_size) {
    if (threadIdx.x == 0) {
        long long base = (long long)T_ * H_;
        if ((long long)out_size >= base + 2) {
            float s = 0.f;
            for (int e = 0; e < E_; e++) {
                float p = g_prob_sum[e] / (float)T_;
                s += p * p;
            }
            out[base] = (float)E_ * s;
            out[base + 1] = g_entropy_sum / (float)T_;
        }
        if ((long long)out_size >= base + 2 + E_) {
            for (int e = 0; e < E_; e++)
                out[base + 2 + e] = (float)g_counts[e];
        }
    }
}

// ---------------- launch ----------------
extern "C" void kernel_launch(void* const* d_in, const int* in_sizes, int n_in,
                              void* d_out, int out_size) {
    const float* x  = (const float*)d_in[0];
    const float* Wr = (const float*)d_in[1];
    const float* br = (const float*)d_in[2];
    const float* W1 = (const float*)d_in[3];
    const float* b1 = (const float*)d_in[4];
    const float* W2 = (const float*)d_in[5];
    const float* b2 = (const float*)d_in[6];
    float* out = (float*)d_out;

    cudaFuncSetAttribute(moe_gemm<H_, D_, true>,
                         cudaFuncAttributeMaxDynamicSharedMemorySize, GEMM_SMEM);
    cudaFuncSetAttribute(moe_gemm<D_, H_, false>,
                         cudaFuncAttributeMaxDynamicSharedMemorySize, GEMM_SMEM);

    init_kernel<<<68, 256>>>();
    router_kernel<<<T_ / 8, 256>>>(x, Wr, br);
    scanscatter_kernel<<<T_ / 256, 256>>>();
    // launch index 3 — the slot ncu captures:
    moe_gemm<H_, D_, true ><<<dim3(D_ / 256, T_ / 128, E_), 256, GEMM_SMEM>>>(x, W1, b1, out);
    moe_gemm<D_, H_, false><<<dim3(H_ / 256, T_ / 128, E_), 256, GEMM_SMEM>>>(x, W2, b2, out);
    finalize_kernel<<<1, 32>>>(out, out_size);
}